// round 1
// baseline (speedup 1.0000x reference)
#include <cuda_runtime.h>
#include <math.h>

#define SEQ 640
#define BATCH 40
#define DIN 8
#define DTRAJ 32
#define DL 64
#define NH 4
#define DH 48
#define EMB 192
#define ROWS (SEQ*BATCH)   // 25600

// ---------------- scratch (device globals; no runtime allocation) ----------------
__device__ float d_gx[ROWS * 256];      // x@W_ih.T + b_ih + b_hh   (26.2 MB)
__device__ float d_seq[ROWS * DL];      // LSTM hidden outputs       (6.55 MB)
__device__ float d_q[ROWS * EMB];
__device__ float d_k[ROWS * EMB];
__device__ float d_v[ROWS * EMB];
__device__ float d_att[ROWS * EMB];     // attention output, heads recombined
__device__ float d_tv2[ROWS * 128];     // [a | g] pre-GLU

__device__ __forceinline__ float sigf(float x) { return 1.f / (1.f + __expf(-x)); }
__device__ __forceinline__ float tanhfast(float x) { return 2.f / (1.f + __expf(-2.f * x)) - 1.f; }

// ---------------- K1: trajectory embed (ELU) + gates_x precompute ----------------
// block = 256 threads handles 8 rows; per-thread W_ih row in registers.
__global__ void __launch_bounds__(256) k1_embed_gates(
    const float* __restrict__ hist, const float* __restrict__ W1,
    const float* __restrict__ b1, const float* __restrict__ W_ih,
    const float* __restrict__ b_ih, const float* __restrict__ b_hh)
{
    __shared__ float xs[8 * 32];
    int tid = threadIdx.x;

    // per-thread weights: W_ih[tid][0..31]
    float4 w4[8];
    const float4* wp = (const float4*)(W_ih + tid * 32);
#pragma unroll
    for (int i = 0; i < 8; i++) w4[i] = wp[i];
    float bsum = b_ih[tid] + b_hh[tid];

    // embed: 8 rows x 32 dims
    int rl = tid >> 5, j = tid & 31;
    int row = blockIdx.x * 8 + rl;
    const float* hp = hist + row * DIN;
    float acc = b1[j];
#pragma unroll
    for (int f = 0; f < DIN; f++) acc = fmaf(hp[f], W1[j * DIN + f], acc);
    xs[rl * 32 + j] = acc > 0.f ? acc : expm1f(acc);
    __syncthreads();

#pragma unroll
    for (int r = 0; r < 8; r++) {
        const float4* xv = (const float4*)(xs + r * 32);
        float g = bsum;
#pragma unroll
        for (int q = 0; q < 8; q++) {
            float4 x4 = xv[q];
            g = fmaf(x4.x, w4[q].x, g);
            g = fmaf(x4.y, w4[q].y, g);
            g = fmaf(x4.z, w4[q].z, g);
            g = fmaf(x4.w, w4[q].w, g);
        }
        d_gx[(blockIdx.x * 8 + r) * 256 + tid] = g;
    }
}

// ---------------- K2: LSTM recurrence, one CTA per batch lane ----------------
__global__ void __launch_bounds__(256) k2_lstm(const float* __restrict__ W_hh)
{
    __shared__ float h_s[64];
    __shared__ float gate_s[256];
    int t = threadIdx.x;        // gate row (0..255): i,f,g,o blocks of 64
    int b = blockIdx.x;         // batch lane

    float4 w[16];
    const float4* wp = (const float4*)(W_hh + t * 64);
#pragma unroll
    for (int i = 0; i < 16; i++) w[i] = wp[i];

    float c = 0.f;
    if (t < 64) h_s[t] = 0.f;
    float gx_cur = d_gx[b * 256 + t];
    __syncthreads();

    for (int step = 0; step < SEQ; step++) {
        float gx_next = 0.f;
        if (step < SEQ - 1) gx_next = d_gx[((step + 1) * BATCH + b) * 256 + t];

        const float4* h4 = (const float4*)h_s;
        float a0 = 0.f, a1 = 0.f, a2 = 0.f, a3 = 0.f;
#pragma unroll
        for (int i = 0; i < 16; i++) {
            float4 hv = h4[i];
            a0 = fmaf(hv.x, w[i].x, a0);
            a1 = fmaf(hv.y, w[i].y, a1);
            a2 = fmaf(hv.z, w[i].z, a2);
            a3 = fmaf(hv.w, w[i].w, a3);
        }
        gate_s[t] = gx_cur + ((a0 + a1) + (a2 + a3));
        __syncthreads();

        if (t < 64) {
            float gi = gate_s[t];
            float gf = gate_s[64 + t];
            float gg = gate_s[128 + t];
            float go = gate_s[192 + t];
            c = sigf(gf) * c + sigf(gi) * tanhfast(gg);
            float hv = sigf(go) * tanhfast(c);
            h_s[t] = hv;
            d_seq[(step * BATCH + b) * 64 + t] = hv;
        }
        __syncthreads();
        gx_cur = gx_next;
    }
}

// ---------------- K3: QKV GEMM  (25600 x 64) @ (64 x 576) ----------------
// 64x64 tile, 256 threads, 4x4 register blocking, smem staged transposed.
__global__ void __launch_bounds__(256) k3_qkv(
    const float* __restrict__ Wq, const float* __restrict__ bq,
    const float* __restrict__ Wk, const float* __restrict__ bk,
    const float* __restrict__ Wv, const float* __restrict__ bv)
{
    __shared__ float As[64 * 68];   // [k][m]
    __shared__ float Bs[64 * 68];   // [k][n]
    int tid = threadIdx.x;
    int mt = blockIdx.x, nt = blockIdx.y;

    const float* W; const float* bias; float* out; int n0;
    if (nt < 3)      { W = Wq; bias = bq; out = d_q; n0 = nt * 64; }
    else if (nt < 6) { W = Wk; bias = bk; out = d_k; n0 = (nt - 3) * 64; }
    else             { W = Wv; bias = bv; out = d_v; n0 = (nt - 6) * 64; }

#pragma unroll
    for (int i = 0; i < 16; i++) {
        int e = tid + i * 256;
        int r = e >> 6, k = e & 63;
        As[k * 68 + r] = d_seq[(mt * 64 + r) * 64 + k];
        Bs[k * 68 + r] = W[(n0 + r) * 64 + k];
    }
    __syncthreads();

    int tx = tid & 15, ty = tid >> 4;
    float acc[4][4] = {};
#pragma unroll
    for (int k = 0; k < 64; k++) {
        float4 a = *(const float4*)&As[k * 68 + ty * 4];
        float4 bb = *(const float4*)&Bs[k * 68 + tx * 4];
        acc[0][0] = fmaf(a.x, bb.x, acc[0][0]); acc[0][1] = fmaf(a.x, bb.y, acc[0][1]);
        acc[0][2] = fmaf(a.x, bb.z, acc[0][2]); acc[0][3] = fmaf(a.x, bb.w, acc[0][3]);
        acc[1][0] = fmaf(a.y, bb.x, acc[1][0]); acc[1][1] = fmaf(a.y, bb.y, acc[1][1]);
        acc[1][2] = fmaf(a.y, bb.z, acc[1][2]); acc[1][3] = fmaf(a.y, bb.w, acc[1][3]);
        acc[2][0] = fmaf(a.z, bb.x, acc[2][0]); acc[2][1] = fmaf(a.z, bb.y, acc[2][1]);
        acc[2][2] = fmaf(a.z, bb.z, acc[2][2]); acc[2][3] = fmaf(a.z, bb.w, acc[2][3]);
        acc[3][0] = fmaf(a.w, bb.x, acc[3][0]); acc[3][1] = fmaf(a.w, bb.y, acc[3][1]);
        acc[3][2] = fmaf(a.w, bb.z, acc[3][2]); acc[3][3] = fmaf(a.w, bb.w, acc[3][3]);
    }
    float4 bv4 = *(const float4*)&bias[n0 + tx * 4];
#pragma unroll
    for (int i = 0; i < 4; i++) {
        int row = mt * 64 + ty * 4 + i;
        float4 o;
        o.x = acc[i][0] + bv4.x; o.y = acc[i][1] + bv4.y;
        o.z = acc[i][2] + bv4.z; o.w = acc[i][3] + bv4.w;
        *(float4*)&out[row * EMB + n0 + tx * 4] = o;
    }
}

// ---------------- K4: attention per (t, head) ----------------
__global__ void __launch_bounds__(256) k4_attn()
{
    __shared__ float qs[40 * 49], ks[40 * 49], vs[40 * 49], ss[40 * 41];
    int t = blockIdx.x, h = blockIdx.y;
    int tid = threadIdx.x;

    for (int e = tid; e < 40 * 48; e += 256) {
        int r = e / 48, d = e - r * 48;
        int src = (t * BATCH + r) * EMB + h * DH + d;
        qs[r * 49 + d] = d_q[src];
        ks[r * 49 + d] = d_k[src];
        vs[r * 49 + d] = d_v[src];
    }
    __syncthreads();

    for (int e = tid; e < 40 * 40; e += 256) {
        int i = e / 40, j = e - i * 40;
        float s = 0.f;
#pragma unroll
        for (int d = 0; d < 48; d++) s = fmaf(qs[i * 49 + d], ks[j * 49 + d], s);
        ss[i * 41 + j] = s * 0.125f;   // / sqrt(64) per reference
    }
    __syncthreads();

    if (tid < 40) {
        float m = -1e30f;
#pragma unroll
        for (int j = 0; j < 40; j++) m = fmaxf(m, ss[tid * 41 + j]);
        float p[40]; float sum = 0.f;
#pragma unroll
        for (int j = 0; j < 40; j++) { p[j] = __expf(ss[tid * 41 + j] - m); sum += p[j]; }
        float inv = 1.f / sum;
#pragma unroll
        for (int j = 0; j < 40; j++) ss[tid * 41 + j] = p[j] * inv;
    }
    __syncthreads();

    for (int e = tid; e < 40 * 48; e += 256) {
        int i = e / 48, d = e - i * 48;
        float s = 0.f;
#pragma unroll
        for (int j = 0; j < 40; j++) s = fmaf(ss[i * 41 + j], vs[j * 49 + d], s);
        d_att[(t * BATCH + i) * EMB + h * DH + d] = s;
    }
}

// ---------------- K5a: GLU GEMM (25600 x 192) @ (192 x 128) ----------------
__global__ void __launch_bounds__(256) k5a_glu_gemm(
    const float* __restrict__ Wa, const float* __restrict__ ba,
    const float* __restrict__ Wg, const float* __restrict__ bg)
{
    __shared__ float As[64 * 68];
    __shared__ float Bs[64 * 68];
    int tid = threadIdx.x;
    int mt = blockIdx.x, nt = blockIdx.y;
    const float* W = nt == 0 ? Wa : Wg;
    const float* bias = nt == 0 ? ba : bg;

    int tx = tid & 15, ty = tid >> 4;
    float acc[4][4] = {};

    for (int kc = 0; kc < 3; kc++) {
#pragma unroll
        for (int i = 0; i < 16; i++) {
            int e = tid + i * 256;
            int r = e >> 6, k = e & 63;
            As[k * 68 + r] = d_att[(mt * 64 + r) * EMB + kc * 64 + k];
            Bs[k * 68 + r] = W[r * EMB + kc * 64 + k];
        }
        __syncthreads();
#pragma unroll
        for (int k = 0; k < 64; k++) {
            float4 a = *(const float4*)&As[k * 68 + ty * 4];
            float4 bb = *(const float4*)&Bs[k * 68 + tx * 4];
            acc[0][0] = fmaf(a.x, bb.x, acc[0][0]); acc[0][1] = fmaf(a.x, bb.y, acc[0][1]);
            acc[0][2] = fmaf(a.x, bb.z, acc[0][2]); acc[0][3] = fmaf(a.x, bb.w, acc[0][3]);
            acc[1][0] = fmaf(a.y, bb.x, acc[1][0]); acc[1][1] = fmaf(a.y, bb.y, acc[1][1]);
            acc[1][2] = fmaf(a.y, bb.z, acc[1][2]); acc[1][3] = fmaf(a.y, bb.w, acc[1][3]);
            acc[2][0] = fmaf(a.z, bb.x, acc[2][0]); acc[2][1] = fmaf(a.z, bb.y, acc[2][1]);
            acc[2][2] = fmaf(a.z, bb.z, acc[2][2]); acc[2][3] = fmaf(a.z, bb.w, acc[2][3]);
            acc[3][0] = fmaf(a.w, bb.x, acc[3][0]); acc[3][1] = fmaf(a.w, bb.y, acc[3][1]);
            acc[3][2] = fmaf(a.w, bb.z, acc[3][2]); acc[3][3] = fmaf(a.w, bb.w, acc[3][3]);
        }
        __syncthreads();
    }
    float4 bv4 = *(const float4*)&bias[tx * 4];
#pragma unroll
    for (int i = 0; i < 4; i++) {
        int row = mt * 64 + ty * 4 + i;
        float4 o;
        o.x = acc[i][0] + bv4.x; o.y = acc[i][1] + bv4.y;
        o.z = acc[i][2] + bv4.z; o.w = acc[i][3] + bv4.w;
        *(float4*)&d_tv2[row * 128 + nt * 64 + tx * 4] = o;
    }
}

// ---------------- K5b: GLU combine + residual + LayerNorm ----------------
__global__ void __launch_bounds__(256) k5b_ln(
    const float* __restrict__ gamma, const float* __restrict__ beta,
    float* __restrict__ out)
{
    __shared__ float ssum[8], ssum2[8];
    int tid = threadIdx.x;
    int grp = tid >> 6;       // 4 rows per block
    int j = tid & 63;
    int row = blockIdx.x * 4 + grp;

    float a = d_tv2[row * 128 + j];
    float g = d_tv2[row * 128 + 64 + j];
    float tv = a * sigf(g);
    float y = d_seq[row * 64 + j] + tv;

    float s = y, s2 = y * y;
#pragma unroll
    for (int off = 16; off; off >>= 1) {
        s += __shfl_xor_sync(0xFFFFFFFFu, s, off);
        s2 += __shfl_xor_sync(0xFFFFFFFFu, s2, off);
    }
    int w = tid >> 5;
    if ((tid & 31) == 0) { ssum[w] = s; ssum2[w] = s2; }
    __syncthreads();
    float tot = ssum[grp * 2] + ssum[grp * 2 + 1];
    float tot2 = ssum2[grp * 2] + ssum2[grp * 2 + 1];
    float mu = tot * (1.f / 64.f);
    float var = tot2 * (1.f / 64.f) - mu * mu;
    float inv = rsqrtf(var + 1e-5f);
    out[row * 64 + j] = (y - mu) * inv * gamma[j] + beta[j];
}

// ---------------- launch ----------------
extern "C" void kernel_launch(void* const* d_in, const int* in_sizes, int n_in,
                              void* d_out, int out_size)
{
    const float* hist = (const float*)d_in[0];
    // d_in[1] = adj (unused, use_spatial=False)
    const float* W1   = (const float*)d_in[2];
    const float* b1   = (const float*)d_in[3];
    const float* W_ih = (const float*)d_in[4];
    const float* W_hh = (const float*)d_in[5];
    const float* b_ih = (const float*)d_in[6];
    const float* b_hh = (const float*)d_in[7];
    const float* Wq   = (const float*)d_in[8];
    const float* bq   = (const float*)d_in[9];
    const float* Wk   = (const float*)d_in[10];
    const float* bk   = (const float*)d_in[11];
    const float* Wv   = (const float*)d_in[12];
    const float* bv   = (const float*)d_in[13];
    const float* Wa   = (const float*)d_in[14];
    const float* ba   = (const float*)d_in[15];
    const float* Wg   = (const float*)d_in[16];
    const float* bg   = (const float*)d_in[17];
    const float* gamma= (const float*)d_in[18];
    const float* beta = (const float*)d_in[19];
    float* out = (float*)d_out;

    k1_embed_gates<<<ROWS / 8, 256>>>(hist, W1, b1, W_ih, b_ih, b_hh);
    k2_lstm<<<BATCH, 256>>>(W_hh);
    k3_qkv<<<dim3(ROWS / 64, 9), 256>>>(Wq, bq, Wk, bk, Wv, bv);
    k4_attn<<<dim3(SEQ, NH), 256>>>();
    k5a_glu_gemm<<<dim3(ROWS / 64, 2), 256>>>(Wa, ba, Wg, bg);
    k5b_ln<<<ROWS / 4, 256>>>(gamma, beta, out);
}

// round 2
// speedup vs baseline: 1.0846x; 1.0846x over previous
#include <cuda_runtime.h>
#include <math.h>

#define SEQ 640
#define BATCH 40
#define DIN 8
#define DL 64
#define NH 4
#define DH 48
#define EMB 192
#define ROWS (SEQ*BATCH)   // 25600

typedef unsigned long long ull;

// ---------------- scratch ----------------
__device__ float d_gx[ROWS * 256];
__device__ float d_seq[ROWS * DL];
__device__ float d_q[ROWS * EMB];
__device__ float d_k[ROWS * EMB];
__device__ float d_v[ROWS * EMB];
__device__ float d_att[ROWS * EMB];
__device__ float d_tv2[ROWS * 128];

__device__ __forceinline__ float sigf(float x) { return 1.f / (1.f + __expf(-x)); }
__device__ __forceinline__ float tanhfast(float x) { return 2.f / (1.f + __expf(-2.f * x)) - 1.f; }

// packed fp32x2 FMA (Blackwell): d = a*b + c lane-wise
__device__ __forceinline__ ull fma2(ull a, ull b, ull c) {
    ull d;
    asm("fma.rn.f32x2 %0, %1, %2, %3;" : "=l"(d) : "l"(a), "l"(b), "l"(c));
    return d;
}
__device__ __forceinline__ float lo32(ull u) { return __uint_as_float((unsigned)u); }
__device__ __forceinline__ float hi32(ull u) { return __uint_as_float((unsigned)(u >> 32)); }
__device__ __forceinline__ float sum2(ull u) { return lo32(u) + hi32(u); }
__device__ __forceinline__ ull dup2(float s) {
    ull d;
    asm("mov.b64 %0, {%1, %1};" : "=l"(d) : "r"(__float_as_uint(s)));
    return d;
}

// ---------------- K1: embed + gates_x ----------------
__global__ void __launch_bounds__(256) k1_embed_gates(
    const float* __restrict__ hist, const float* __restrict__ W1,
    const float* __restrict__ b1, const float* __restrict__ W_ih,
    const float* __restrict__ b_ih, const float* __restrict__ b_hh)
{
    __shared__ __align__(16) float xs[8 * 32];
    int tid = threadIdx.x;

    ull w2[16];
    const ull* wp = (const ull*)(W_ih + tid * 32);
#pragma unroll
    for (int i = 0; i < 16; i++) w2[i] = wp[i];
    float bsum = b_ih[tid] + b_hh[tid];

    int rl = tid >> 5, j = tid & 31;
    const float* hp = hist + (blockIdx.x * 8 + rl) * DIN;
    float acc = b1[j];
#pragma unroll
    for (int f = 0; f < DIN; f++) acc = fmaf(hp[f], W1[j * DIN + f], acc);
    xs[rl * 32 + j] = acc > 0.f ? acc : expm1f(acc);
    __syncthreads();

#pragma unroll
    for (int r = 0; r < 8; r++) {
        const ulonglong2* xv = (const ulonglong2*)(xs + r * 32);
        ull s0 = 0, s1 = 0;
#pragma unroll
        for (int q = 0; q < 8; q++) {
            ulonglong2 x2 = xv[q];
            s0 = fma2(x2.x, w2[2 * q], s0);
            s1 = fma2(x2.y, w2[2 * q + 1], s1);
        }
        d_gx[(blockIdx.x * 8 + r) * 256 + tid] = bsum + (sum2(s0) + sum2(s1));
    }
}

// ---------------- K2: LSTM recurrence ----------------
__global__ void __launch_bounds__(256) k2_lstm(const float* __restrict__ W_hh)
{
    __shared__ __align__(16) float h_s[64];
    __shared__ float gate_s[256];
    int t = threadIdx.x;
    int b = blockIdx.x;
    int grp = t >> 6;

    ull w2[32];
    const ull* wp = (const ull*)(W_hh + t * 64);
#pragma unroll
    for (int i = 0; i < 32; i++) w2[i] = wp[i];

    float c = 0.f;
    if (t < 64) h_s[t] = 0.f;
    float gx_cur = d_gx[b * 256 + t];
    __syncthreads();

    for (int step = 0; step < SEQ; step++) {
        float gx_next = 0.f;
        if (step < SEQ - 1) gx_next = d_gx[((step + 1) * BATCH + b) * 256 + t];

        const ulonglong2* h2 = (const ulonglong2*)h_s;
        ull a0 = 0, a1 = 0, a2 = 0, a3 = 0;
#pragma unroll
        for (int i = 0; i < 8; i++) {
            ulonglong2 p = h2[2 * i], q = h2[2 * i + 1];
            a0 = fma2(p.x, w2[4 * i + 0], a0);
            a1 = fma2(p.y, w2[4 * i + 1], a1);
            a2 = fma2(q.x, w2[4 * i + 2], a2);
            a3 = fma2(q.y, w2[4 * i + 3], a3);
        }
        float gate = gx_cur + ((sum2(a0) + sum2(a1)) + (sum2(a2) + sum2(a3)));
        // pre-activate: i,f,o -> sigmoid, g -> tanh (done by ALL 256 threads in parallel)
        float act = (grp == 2) ? tanhfast(gate) : sigf(gate);
        gate_s[t] = act;
        __syncthreads();

        if (t < 64) {
            float ai = gate_s[t];
            float af = gate_s[64 + t];
            float ag = gate_s[128 + t];
            float ao = gate_s[192 + t];
            c = af * c + ai * ag;
            float hv = ao * tanhfast(c);
            h_s[t] = hv;
            d_seq[(step * BATCH + b) * 64 + t] = hv;
        }
        __syncthreads();
        gx_cur = gx_next;
    }
}

// ---------------- K3: QKV GEMM 128x64 tile, 8x8/thread, f32x2 ----------------
__global__ void __launch_bounds__(128) k3_qkv(
    const float* __restrict__ Wq, const float* __restrict__ bq,
    const float* __restrict__ Wk, const float* __restrict__ bk,
    const float* __restrict__ Wv, const float* __restrict__ bv)
{
    __shared__ __align__(16) float As[16 * 256];  // [k2][m] as float2 pairs
    __shared__ __align__(16) float Bs[16 * 128];  // [k2][n]
    int tid = threadIdx.x;
    int mt = blockIdx.x, nt = blockIdx.y;

    const float* W; const float* bias; float* out; int n0;
    if (nt < 3)      { W = Wq; bias = bq; out = d_q; n0 = nt * 64; }
    else if (nt < 6) { W = Wk; bias = bk; out = d_k; n0 = (nt - 3) * 64; }
    else             { W = Wv; bias = bv; out = d_v; n0 = (nt - 6) * 64; }

    int tx = tid & 7, ty = tid >> 3;
    int m0 = ty * 8, nn0 = tx * 8;
    ull acc[8][8] = {};

    int rB = tid & 63, hf = tid >> 6;

    for (int kc = 0; kc < 2; kc++) {
#pragma unroll
        for (int i = 0; i < 8; i++) {
            float4 v = *(const float4*)&d_seq[(mt * 128 + tid) * 64 + kc * 32 + i * 4];
            *(float2*)&As[(i * 2) * 256 + tid * 2] = make_float2(v.x, v.y);
            *(float2*)&As[(i * 2 + 1) * 256 + tid * 2] = make_float2(v.z, v.w);
        }
#pragma unroll
        for (int i = 0; i < 4; i++) {
            int c4 = i * 2 + hf;
            float4 v = *(const float4*)&W[(n0 + rB) * 64 + kc * 32 + c4 * 4];
            *(float2*)&Bs[(c4 * 2) * 128 + rB * 2] = make_float2(v.x, v.y);
            *(float2*)&Bs[(c4 * 2 + 1) * 128 + rB * 2] = make_float2(v.z, v.w);
        }
        __syncthreads();
#pragma unroll
        for (int k2 = 0; k2 < 16; k2++) {
            ulonglong2 a01 = *(const ulonglong2*)&As[k2 * 256 + m0 * 2];
            ulonglong2 a23 = *(const ulonglong2*)&As[k2 * 256 + m0 * 2 + 4];
            ulonglong2 a45 = *(const ulonglong2*)&As[k2 * 256 + m0 * 2 + 8];
            ulonglong2 a67 = *(const ulonglong2*)&As[k2 * 256 + m0 * 2 + 12];
            ulonglong2 b01 = *(const ulonglong2*)&Bs[k2 * 128 + nn0 * 2];
            ulonglong2 b23 = *(const ulonglong2*)&Bs[k2 * 128 + nn0 * 2 + 4];
            ulonglong2 b45 = *(const ulonglong2*)&Bs[k2 * 128 + nn0 * 2 + 8];
            ulonglong2 b67 = *(const ulonglong2*)&Bs[k2 * 128 + nn0 * 2 + 12];
            ull av[8] = {a01.x, a01.y, a23.x, a23.y, a45.x, a45.y, a67.x, a67.y};
            ull bv_[8] = {b01.x, b01.y, b23.x, b23.y, b45.x, b45.y, b67.x, b67.y};
#pragma unroll
            for (int i = 0; i < 8; i++)
#pragma unroll
                for (int j = 0; j < 8; j++)
                    acc[i][j] = fma2(av[i], bv_[j], acc[i][j]);
        }
        __syncthreads();
    }
    float4 bv0 = *(const float4*)&bias[n0 + nn0];
    float4 bv1 = *(const float4*)&bias[n0 + nn0 + 4];
#pragma unroll
    for (int i = 0; i < 8; i++) {
        int row = mt * 128 + m0 + i;
        float4 o0, o1;
        o0.x = sum2(acc[i][0]) + bv0.x; o0.y = sum2(acc[i][1]) + bv0.y;
        o0.z = sum2(acc[i][2]) + bv0.z; o0.w = sum2(acc[i][3]) + bv0.w;
        o1.x = sum2(acc[i][4]) + bv1.x; o1.y = sum2(acc[i][5]) + bv1.y;
        o1.z = sum2(acc[i][6]) + bv1.z; o1.w = sum2(acc[i][7]) + bv1.w;
        *(float4*)&out[row * EMB + n0 + nn0] = o0;
        *(float4*)&out[row * EMB + n0 + nn0 + 4] = o1;
    }
}

// ---------------- K4: attention, register-tiled ----------------
__global__ void __launch_bounds__(128) k4_attn()
{
    __shared__ __align__(16) float qs[40 * 52];
    __shared__ __align__(16) float ks[40 * 52];
    __shared__ __align__(16) float vs[40 * 52];
    __shared__ float ss[40 * 44];
    int t = blockIdx.x, h = blockIdx.y;
    int tid = threadIdx.x;

    for (int e = tid; e < 1440; e += 128) {
        int arr = e / 480, idx = e - arr * 480;
        int r = idx / 12, c4 = idx - r * 12;
        const float* src = arr == 0 ? d_q : (arr == 1 ? d_k : d_v);
        float* dst = arr == 0 ? qs : (arr == 1 ? ks : vs);
        float4 v = *(const float4*)&src[(t * BATCH + r) * EMB + h * DH + c4 * 4];
        *(float4*)&dst[r * 52 + c4 * 4] = v;
    }
    __syncthreads();

    // S = Q K^T / 8 : 5x10 grid of 8x4 tiles, k paired
    if (tid < 50) {
        int it = tid / 10, jt = tid - it * 10;
        int i0 = it * 8, j0 = jt * 4;
        ull acc[8][4] = {};
#pragma unroll
        for (int kk = 0; kk < 12; kk++) {
            ulonglong2 Q[8];
#pragma unroll
            for (int i = 0; i < 8; i++) Q[i] = *(const ulonglong2*)&qs[(i0 + i) * 52 + kk * 4];
            ulonglong2 Kv[4];
#pragma unroll
            for (int j = 0; j < 4; j++) Kv[j] = *(const ulonglong2*)&ks[(j0 + j) * 52 + kk * 4];
#pragma unroll
            for (int i = 0; i < 8; i++)
#pragma unroll
                for (int j = 0; j < 4; j++) {
                    acc[i][j] = fma2(Q[i].x, Kv[j].x, acc[i][j]);
                    acc[i][j] = fma2(Q[i].y, Kv[j].y, acc[i][j]);
                }
        }
#pragma unroll
        for (int i = 0; i < 8; i++)
#pragma unroll
            for (int j = 0; j < 4; j++)
                ss[(i0 + i) * 44 + j0 + j] = sum2(acc[i][j]) * 0.125f;
    }
    __syncthreads();

    if (tid < 40) {
        float m = -1e30f;
#pragma unroll
        for (int j = 0; j < 40; j++) m = fmaxf(m, ss[tid * 44 + j]);
        float p[40]; float sum = 0.f;
#pragma unroll
        for (int j = 0; j < 40; j++) { p[j] = __expf(ss[tid * 44 + j] - m); sum += p[j]; }
        float inv = 1.f / sum;
#pragma unroll
        for (int j = 0; j < 40; j++) ss[tid * 44 + j] = p[j] * inv;
    }
    __syncthreads();

    // O = P V : 10x4 grid of 4x12 tiles, d paired
    if (tid < 40) {
        int it = tid >> 2, dt = tid & 3;
        int i0 = it * 4, d0 = dt * 12;
        ull acc[4][6] = {};
        for (int j = 0; j < 40; j++) {
            ull sp[4];
#pragma unroll
            for (int i = 0; i < 4; i++) sp[i] = dup2(ss[(i0 + i) * 44 + j]);
            ulonglong2 v0 = *(const ulonglong2*)&vs[j * 52 + d0];
            ulonglong2 v1 = *(const ulonglong2*)&vs[j * 52 + d0 + 4];
            ulonglong2 v2 = *(const ulonglong2*)&vs[j * 52 + d0 + 8];
            ull vp[6] = {v0.x, v0.y, v1.x, v1.y, v2.x, v2.y};
#pragma unroll
            for (int i = 0; i < 4; i++)
#pragma unroll
                for (int p = 0; p < 6; p++)
                    acc[i][p] = fma2(sp[i], vp[p], acc[i][p]);
        }
#pragma unroll
        for (int i = 0; i < 4; i++) {
            float* op = &d_att[(t * BATCH + i0 + i) * EMB + h * DH + d0];
            float4 o0, o1, o2;
            o0.x = lo32(acc[i][0]); o0.y = hi32(acc[i][0]); o0.z = lo32(acc[i][1]); o0.w = hi32(acc[i][1]);
            o1.x = lo32(acc[i][2]); o1.y = hi32(acc[i][2]); o1.z = lo32(acc[i][3]); o1.w = hi32(acc[i][3]);
            o2.x = lo32(acc[i][4]); o2.y = hi32(acc[i][4]); o2.z = lo32(acc[i][5]); o2.w = hi32(acc[i][5]);
            *(float4*)&op[0] = o0;
            *(float4*)&op[4] = o1;
            *(float4*)&op[8] = o2;
        }
    }
}

// ---------------- K5a: GLU GEMM 128x64 tile, K=192 in 6 chunks ----------------
__global__ void __launch_bounds__(128) k5a_glu_gemm(
    const float* __restrict__ Wa, const float* __restrict__ ba,
    const float* __restrict__ Wg, const float* __restrict__ bg)
{
    __shared__ __align__(16) float As[16 * 256];
    __shared__ __align__(16) float Bs[16 * 128];
    int tid = threadIdx.x;
    int mt = blockIdx.x, nt = blockIdx.y;
    const float* W = nt == 0 ? Wa : Wg;
    const float* bias = nt == 0 ? ba : bg;

    int tx = tid & 7, ty = tid >> 3;
    int m0 = ty * 8, nn0 = tx * 8;
    ull acc[8][8] = {};
    int rB = tid & 63, hf = tid >> 6;

    for (int kc = 0; kc < 6; kc++) {
#pragma unroll
        for (int i = 0; i < 8; i++) {
            float4 v = *(const float4*)&d_att[(mt * 128 + tid) * EMB + kc * 32 + i * 4];
            *(float2*)&As[(i * 2) * 256 + tid * 2] = make_float2(v.x, v.y);
            *(float2*)&As[(i * 2 + 1) * 256 + tid * 2] = make_float2(v.z, v.w);
        }
#pragma unroll
        for (int i = 0; i < 4; i++) {
            int c4 = i * 2 + hf;
            float4 v = *(const float4*)&W[rB * EMB + kc * 32 + c4 * 4];
            *(float2*)&Bs[(c4 * 2) * 128 + rB * 2] = make_float2(v.x, v.y);
            *(float2*)&Bs[(c4 * 2 + 1) * 128 + rB * 2] = make_float2(v.z, v.w);
        }
        __syncthreads();
#pragma unroll
        for (int k2 = 0; k2 < 16; k2++) {
            ulonglong2 a01 = *(const ulonglong2*)&As[k2 * 256 + m0 * 2];
            ulonglong2 a23 = *(const ulonglong2*)&As[k2 * 256 + m0 * 2 + 4];
            ulonglong2 a45 = *(const ulonglong2*)&As[k2 * 256 + m0 * 2 + 8];
            ulonglong2 a67 = *(const ulonglong2*)&As[k2 * 256 + m0 * 2 + 12];
            ulonglong2 b01 = *(const ulonglong2*)&Bs[k2 * 128 + nn0 * 2];
            ulonglong2 b23 = *(const ulonglong2*)&Bs[k2 * 128 + nn0 * 2 + 4];
            ulonglong2 b45 = *(const ulonglong2*)&Bs[k2 * 128 + nn0 * 2 + 8];
            ulonglong2 b67 = *(const ulonglong2*)&Bs[k2 * 128 + nn0 * 2 + 12];
            ull av[8] = {a01.x, a01.y, a23.x, a23.y, a45.x, a45.y, a67.x, a67.y};
            ull bv_[8] = {b01.x, b01.y, b23.x, b23.y, b45.x, b45.y, b67.x, b67.y};
#pragma unroll
            for (int i = 0; i < 8; i++)
#pragma unroll
                for (int j = 0; j < 8; j++)
                    acc[i][j] = fma2(av[i], bv_[j], acc[i][j]);
        }
        __syncthreads();
    }
    float4 bv0 = *(const float4*)&bias[nn0];
    float4 bv1 = *(const float4*)&bias[nn0 + 4];
#pragma unroll
    for (int i = 0; i < 8; i++) {
        int row = mt * 128 + m0 + i;
        float4 o0, o1;
        o0.x = sum2(acc[i][0]) + bv0.x; o0.y = sum2(acc[i][1]) + bv0.y;
        o0.z = sum2(acc[i][2]) + bv0.z; o0.w = sum2(acc[i][3]) + bv0.w;
        o1.x = sum2(acc[i][4]) + bv1.x; o1.y = sum2(acc[i][5]) + bv1.y;
        o1.z = sum2(acc[i][6]) + bv1.z; o1.w = sum2(acc[i][7]) + bv1.w;
        *(float4*)&d_tv2[row * 128 + nt * 64 + nn0] = o0;
        *(float4*)&d_tv2[row * 128 + nt * 64 + nn0 + 4] = o1;
    }
}

// ---------------- K5b: GLU + residual + LayerNorm ----------------
__global__ void __launch_bounds__(256) k5b_ln(
    const float* __restrict__ gamma, const float* __restrict__ beta,
    float* __restrict__ out)
{
    __shared__ float ssum[8], ssum2[8];
    int tid = threadIdx.x;
    int grp = tid >> 6;
    int j = tid & 63;
    int row = blockIdx.x * 4 + grp;

    float a = d_tv2[row * 128 + j];
    float g = d_tv2[row * 128 + 64 + j];
    float y = d_seq[row * 64 + j] + a * sigf(g);

    float s = y, s2 = y * y;
#pragma unroll
    for (int off = 16; off; off >>= 1) {
        s += __shfl_xor_sync(0xFFFFFFFFu, s, off);
        s2 += __shfl_xor_sync(0xFFFFFFFFu, s2, off);
    }
    int w = tid >> 5;
    if ((tid & 31) == 0) { ssum[w] = s; ssum2[w] = s2; }
    __syncthreads();
    float tot = ssum[grp * 2] + ssum[grp * 2 + 1];
    float tot2 = ssum2[grp * 2] + ssum2[grp * 2 + 1];
    float mu = tot * (1.f / 64.f);
    float var = tot2 * (1.f / 64.f) - mu * mu;
    float inv = rsqrtf(var + 1e-5f);
    out[row * 64 + j] = (y - mu) * inv * gamma[j] + beta[j];
}

// ---------------- launch ----------------
extern "C" void kernel_launch(void* const* d_in, const int* in_sizes, int n_in,
                              void* d_out, int out_size)
{
    const float* hist = (const float*)d_in[0];
    const float* W1   = (const float*)d_in[2];
    const float* b1   = (const float*)d_in[3];
    const float* W_ih = (const float*)d_in[4];
    const float* W_hh = (const float*)d_in[5];
    const float* b_ih = (const float*)d_in[6];
    const float* b_hh = (const float*)d_in[7];
    const float* Wq   = (const float*)d_in[8];
    const float* bq   = (const float*)d_in[9];
    const float* Wk   = (const float*)d_in[10];
    const float* bk   = (const float*)d_in[11];
    const float* Wv   = (const float*)d_in[12];
    const float* bv   = (const float*)d_in[13];
    const float* Wa   = (const float*)d_in[14];
    const float* ba   = (const float*)d_in[15];
    const float* Wg   = (const float*)d_in[16];
    const float* bg   = (const float*)d_in[17];
    const float* gamma= (const float*)d_in[18];
    const float* beta = (const float*)d_in[19];
    float* out = (float*)d_out;

    k1_embed_gates<<<ROWS / 8, 256>>>(hist, W1, b1, W_ih, b_ih, b_hh);
    k2_lstm<<<BATCH, 256>>>(W_hh);
    k3_qkv<<<dim3(ROWS / 128, 9), 128>>>(Wq, bq, Wk, bk, Wv, bv);
    k4_attn<<<dim3(SEQ, NH), 128>>>();
    k5a_glu_gemm<<<dim3(ROWS / 128, 2), 128>>>(Wa, ba, Wg, bg);
    k5b_ln<<<ROWS / 4, 256>>>(gamma, beta, out);
}

// round 3
// speedup vs baseline: 1.2093x; 1.1150x over previous
#include <cuda_runtime.h>
#include <math.h>

#define SEQ 640
#define BATCH 40
#define DIN 8
#define DL 64
#define NH 4
#define DH 48
#define EMB 192
#define ROWS (SEQ*BATCH)   // 25600

typedef unsigned long long ull;

// ---------------- scratch ----------------
__device__ float d_gx[ROWS * 256];
__device__ float d_seq[ROWS * DL];
__device__ float d_q[ROWS * EMB];
__device__ float d_k[ROWS * EMB];
__device__ float d_v[ROWS * EMB];
__device__ float d_att[ROWS * EMB];
__device__ float d_tv2[ROWS * 128];

__device__ __forceinline__ float sigf(float x) { return 1.f / (1.f + __expf(-x)); }
__device__ __forceinline__ float tanhfast(float x) { return 2.f / (1.f + __expf(-2.f * x)) - 1.f; }

__device__ __forceinline__ ull fma2(ull a, ull b, ull c) {
    ull d;
    asm("fma.rn.f32x2 %0, %1, %2, %3;" : "=l"(d) : "l"(a), "l"(b), "l"(c));
    return d;
}
__device__ __forceinline__ float lo32(ull u) { return __uint_as_float((unsigned)u); }
__device__ __forceinline__ float hi32(ull u) { return __uint_as_float((unsigned)(u >> 32)); }
__device__ __forceinline__ float sum2(ull u) { return lo32(u) + hi32(u); }
__device__ __forceinline__ ull dup2(float s) {
    ull d;
    asm("mov.b64 %0, {%1, %1};" : "=l"(d) : "r"(__float_as_uint(s)));
    return d;
}

// ---------------- K1: embed + gates_x ----------------
__global__ void __launch_bounds__(256) k1_embed_gates(
    const float* __restrict__ hist, const float* __restrict__ W1,
    const float* __restrict__ b1, const float* __restrict__ W_ih,
    const float* __restrict__ b_ih, const float* __restrict__ b_hh)
{
    __shared__ __align__(16) float xs[8 * 32];
    int tid = threadIdx.x;

    ull w2[16];
    const ull* wp = (const ull*)(W_ih + tid * 32);
#pragma unroll
    for (int i = 0; i < 16; i++) w2[i] = wp[i];
    float bsum = b_ih[tid] + b_hh[tid];

    int rl = tid >> 5, j = tid & 31;
    const float* hp = hist + (blockIdx.x * 8 + rl) * DIN;
    float acc = b1[j];
#pragma unroll
    for (int f = 0; f < DIN; f++) acc = fmaf(hp[f], W1[j * DIN + f], acc);
    xs[rl * 32 + j] = acc > 0.f ? acc : expm1f(acc);
    __syncthreads();

#pragma unroll
    for (int r = 0; r < 8; r++) {
        const ulonglong2* xv = (const ulonglong2*)(xs + r * 32);
        ull s0 = 0, s1 = 0;
#pragma unroll
        for (int q = 0; q < 8; q++) {
            ulonglong2 x2 = xv[q];
            s0 = fma2(x2.x, w2[2 * q], s0);
            s1 = fma2(x2.y, w2[2 * q + 1], s1);
        }
        d_gx[(blockIdx.x * 8 + r) * 256 + tid] = bsum + (sum2(s0) + sum2(s1));
    }
}

// ---------------- K2: LSTM recurrence ----------------
__global__ void __launch_bounds__(256) k2_lstm(const float* __restrict__ W_hh)
{
    __shared__ __align__(16) float h_s[64];
    __shared__ float gate_s[256];
    int t = threadIdx.x;
    int b = blockIdx.x;
    int grp = t >> 6;

    ull w2[32];
    const ull* wp = (const ull*)(W_hh + t * 64);
#pragma unroll
    for (int i = 0; i < 32; i++) w2[i] = wp[i];

    float c = 0.f;
    if (t < 64) h_s[t] = 0.f;
    float gx_cur = d_gx[b * 256 + t];
    __syncthreads();

    for (int step = 0; step < SEQ; step++) {
        float gx_next = 0.f;
        if (step < SEQ - 1) gx_next = d_gx[((step + 1) * BATCH + b) * 256 + t];

        const ulonglong2* h2 = (const ulonglong2*)h_s;
        ull a0 = 0, a1 = 0, a2 = 0, a3 = 0;
#pragma unroll
        for (int i = 0; i < 8; i++) {
            ulonglong2 p = h2[2 * i], q = h2[2 * i + 1];
            a0 = fma2(p.x, w2[4 * i + 0], a0);
            a1 = fma2(p.y, w2[4 * i + 1], a1);
            a2 = fma2(q.x, w2[4 * i + 2], a2);
            a3 = fma2(q.y, w2[4 * i + 3], a3);
        }
        float gate = gx_cur + ((sum2(a0) + sum2(a1)) + (sum2(a2) + sum2(a3)));
        float act = (grp == 2) ? tanhfast(gate) : sigf(gate);
        gate_s[t] = act;
        __syncthreads();

        if (t < 64) {
            float ai = gate_s[t];
            float af = gate_s[64 + t];
            float ag = gate_s[128 + t];
            float ao = gate_s[192 + t];
            c = af * c + ai * ag;
            float hv = ao * tanhfast(c);
            h_s[t] = hv;
            d_seq[(step * BATCH + b) * 64 + t] = hv;
        }
        __syncthreads();
        gx_cur = gx_next;
    }
}

// ---------------- K3: QKV GEMM 128x64 tile, 256 thr, 8x4/thread ----------------
__global__ void __launch_bounds__(256) k3_qkv(
    const float* __restrict__ Wq, const float* __restrict__ bq,
    const float* __restrict__ Wk, const float* __restrict__ bk,
    const float* __restrict__ Wv, const float* __restrict__ bv)
{
    __shared__ __align__(16) float As[16 * 256];  // [k2][m pairs]
    __shared__ __align__(16) float Bs[16 * 128];  // [k2][n pairs]
    int tid = threadIdx.x;
    int mt = blockIdx.x, nt = blockIdx.y;

    const float* W; const float* bias; float* out; int n0;
    if (nt < 3)      { W = Wq; bias = bq; out = d_q; n0 = nt * 64; }
    else if (nt < 6) { W = Wk; bias = bk; out = d_k; n0 = (nt - 3) * 64; }
    else             { W = Wv; bias = bv; out = d_v; n0 = (nt - 6) * 64; }

    int tx = tid & 15, ty = tid >> 4;
    int m0 = ty * 8, nn0 = tx * 4;
    ull acc[8][4] = {};

    for (int kc = 0; kc < 2; kc++) {
#pragma unroll
        for (int i = 0; i < 4; i++) {
            int e = tid + i * 256;
            int r = e & 127, c4 = e >> 7;
            float4 v = *(const float4*)&d_seq[(mt * 128 + r) * 64 + kc * 32 + c4 * 4];
            *(float2*)&As[(c4 * 2) * 256 + r * 2] = make_float2(v.x, v.y);
            *(float2*)&As[(c4 * 2 + 1) * 256 + r * 2] = make_float2(v.z, v.w);
        }
#pragma unroll
        for (int i = 0; i < 2; i++) {
            int e = tid + i * 256;
            int r = e & 63, c4 = e >> 6;
            float4 v = *(const float4*)&W[(n0 + r) * 64 + kc * 32 + c4 * 4];
            *(float2*)&Bs[(c4 * 2) * 128 + r * 2] = make_float2(v.x, v.y);
            *(float2*)&Bs[(c4 * 2 + 1) * 128 + r * 2] = make_float2(v.z, v.w);
        }
        __syncthreads();
#pragma unroll
        for (int k2 = 0; k2 < 16; k2++) {
            ulonglong2 a01 = *(const ulonglong2*)&As[k2 * 256 + m0 * 2];
            ulonglong2 a23 = *(const ulonglong2*)&As[k2 * 256 + m0 * 2 + 4];
            ulonglong2 a45 = *(const ulonglong2*)&As[k2 * 256 + m0 * 2 + 8];
            ulonglong2 a67 = *(const ulonglong2*)&As[k2 * 256 + m0 * 2 + 12];
            ulonglong2 b01 = *(const ulonglong2*)&Bs[k2 * 128 + nn0 * 2];
            ulonglong2 b23 = *(const ulonglong2*)&Bs[k2 * 128 + nn0 * 2 + 4];
            ull av[8] = {a01.x, a01.y, a23.x, a23.y, a45.x, a45.y, a67.x, a67.y};
            ull bv_[4] = {b01.x, b01.y, b23.x, b23.y};
#pragma unroll
            for (int i = 0; i < 8; i++)
#pragma unroll
                for (int j = 0; j < 4; j++)
                    acc[i][j] = fma2(av[i], bv_[j], acc[i][j]);
        }
        __syncthreads();
    }
    float4 bv4 = *(const float4*)&bias[n0 + nn0];
#pragma unroll
    for (int i = 0; i < 8; i++) {
        int row = mt * 128 + m0 + i;
        float4 o;
        o.x = sum2(acc[i][0]) + bv4.x; o.y = sum2(acc[i][1]) + bv4.y;
        o.z = sum2(acc[i][2]) + bv4.z; o.w = sum2(acc[i][3]) + bv4.w;
        *(float4*)&out[row * EMB + n0 + nn0] = o;
    }
}

// ---------------- K4: attention, 160 threads, all active ----------------
__global__ void __launch_bounds__(160) k4_attn()
{
    __shared__ __align__(16) float qs[40 * 52];
    __shared__ __align__(16) float ks[40 * 52];
    __shared__ __align__(16) float vs[40 * 52];
    __shared__ float ss[40 * 41];
    int t = blockIdx.x, h = blockIdx.y;
    int tid = threadIdx.x;

#pragma unroll
    for (int ii = 0; ii < 9; ii++) {
        int e = tid + ii * 160;
        int arr = e / 480, idx = e - arr * 480;
        int r = idx / 12, c4 = idx - r * 12;
        const float* src = arr == 0 ? d_q : (arr == 1 ? d_k : d_v);
        float* dst = arr == 0 ? qs : (arr == 1 ? ks : vs);
        float4 v = *(const float4*)&src[(t * BATCH + r) * EMB + h * DH + c4 * 4];
        *(float4*)&dst[r * 52 + c4 * 4] = v;
    }
    __syncthreads();

    int i = tid % 40;
    int ct = tid / 40;     // 0..3

    // S = Q K^T / 8 : each thread: row i vs 10 K-rows
    {
        int j0 = ct * 10;
        ull acc[10] = {};
#pragma unroll
        for (int kk = 0; kk < 12; kk++) {
            ulonglong2 q2 = *(const ulonglong2*)&qs[i * 52 + kk * 4];
#pragma unroll
            for (int jj = 0; jj < 10; jj++) {
                ulonglong2 k2v = *(const ulonglong2*)&ks[(j0 + jj) * 52 + kk * 4];
                acc[jj] = fma2(q2.x, k2v.x, acc[jj]);
                acc[jj] = fma2(q2.y, k2v.y, acc[jj]);
            }
        }
#pragma unroll
        for (int jj = 0; jj < 10; jj++)
            ss[i * 41 + j0 + jj] = sum2(acc[jj]) * 0.125f;
    }
    __syncthreads();

    if (tid < 40) {
        float m = -1e30f;
#pragma unroll
        for (int j = 0; j < 40; j++) m = fmaxf(m, ss[tid * 41 + j]);
        float p[40]; float sum = 0.f;
#pragma unroll
        for (int j = 0; j < 40; j++) { p[j] = __expf(ss[tid * 41 + j] - m); sum += p[j]; }
        float inv = 1.f / sum;
#pragma unroll
        for (int j = 0; j < 40; j++) ss[tid * 41 + j] = p[j] * inv;
    }
    __syncthreads();

    // O = P V : each thread: row i, d-chunk of 12
    {
        int d0 = ct * 12;
        ull acc[6] = {};
#pragma unroll
        for (int j = 0; j < 40; j++) {
            ull sp = dup2(ss[i * 41 + j]);
            ulonglong2 v0 = *(const ulonglong2*)&vs[j * 52 + d0];
            ulonglong2 v1 = *(const ulonglong2*)&vs[j * 52 + d0 + 4];
            ulonglong2 v2 = *(const ulonglong2*)&vs[j * 52 + d0 + 8];
            acc[0] = fma2(sp, v0.x, acc[0]);
            acc[1] = fma2(sp, v0.y, acc[1]);
            acc[2] = fma2(sp, v1.x, acc[2]);
            acc[3] = fma2(sp, v1.y, acc[3]);
            acc[4] = fma2(sp, v2.x, acc[4]);
            acc[5] = fma2(sp, v2.y, acc[5]);
        }
        float* op = &d_att[(t * BATCH + i) * EMB + h * DH + d0];
        float4 o0, o1, o2;
        o0.x = lo32(acc[0]); o0.y = hi32(acc[0]); o0.z = lo32(acc[1]); o0.w = hi32(acc[1]);
        o1.x = lo32(acc[2]); o1.y = hi32(acc[2]); o1.z = lo32(acc[3]); o1.w = hi32(acc[3]);
        o2.x = lo32(acc[4]); o2.y = hi32(acc[4]); o2.z = lo32(acc[5]); o2.w = hi32(acc[5]);
        *(float4*)&op[0] = o0;
        *(float4*)&op[4] = o1;
        *(float4*)&op[8] = o2;
    }
}

// ---------------- K5a: GLU GEMM 128x64 tile, 256 thr, 8x4/thread ----------------
__global__ void __launch_bounds__(256) k5a_glu_gemm(
    const float* __restrict__ Wa, const float* __restrict__ ba,
    const float* __restrict__ Wg, const float* __restrict__ bg)
{
    __shared__ __align__(16) float As[16 * 256];
    __shared__ __align__(16) float Bs[16 * 128];
    int tid = threadIdx.x;
    int mt = blockIdx.x, nt = blockIdx.y;
    const float* W = nt == 0 ? Wa : Wg;
    const float* bias = nt == 0 ? ba : bg;

    int tx = tid & 15, ty = tid >> 4;
    int m0 = ty * 8, nn0 = tx * 4;
    ull acc[8][4] = {};

    for (int kc = 0; kc < 6; kc++) {
#pragma unroll
        for (int i = 0; i < 4; i++) {
            int e = tid + i * 256;
            int r = e & 127, c4 = e >> 7;
            float4 v = *(const float4*)&d_att[(mt * 128 + r) * EMB + kc * 32 + c4 * 4];
            *(float2*)&As[(c4 * 2) * 256 + r * 2] = make_float2(v.x, v.y);
            *(float2*)&As[(c4 * 2 + 1) * 256 + r * 2] = make_float2(v.z, v.w);
        }
#pragma unroll
        for (int i = 0; i < 2; i++) {
            int e = tid + i * 256;
            int r = e & 63, c4 = e >> 6;
            float4 v = *(const float4*)&W[r * EMB + kc * 32 + c4 * 4];
            *(float2*)&Bs[(c4 * 2) * 128 + r * 2] = make_float2(v.x, v.y);
            *(float2*)&Bs[(c4 * 2 + 1) * 128 + r * 2] = make_float2(v.z, v.w);
        }
        __syncthreads();
#pragma unroll
        for (int k2 = 0; k2 < 16; k2++) {
            ulonglong2 a01 = *(const ulonglong2*)&As[k2 * 256 + m0 * 2];
            ulonglong2 a23 = *(const ulonglong2*)&As[k2 * 256 + m0 * 2 + 4];
            ulonglong2 a45 = *(const ulonglong2*)&As[k2 * 256 + m0 * 2 + 8];
            ulonglong2 a67 = *(const ulonglong2*)&As[k2 * 256 + m0 * 2 + 12];
            ulonglong2 b01 = *(const ulonglong2*)&Bs[k2 * 128 + nn0 * 2];
            ulonglong2 b23 = *(const ulonglong2*)&Bs[k2 * 128 + nn0 * 2 + 4];
            ull av[8] = {a01.x, a01.y, a23.x, a23.y, a45.x, a45.y, a67.x, a67.y};
            ull bv_[4] = {b01.x, b01.y, b23.x, b23.y};
#pragma unroll
            for (int i = 0; i < 8; i++)
#pragma unroll
                for (int j = 0; j < 4; j++)
                    acc[i][j] = fma2(av[i], bv_[j], acc[i][j]);
        }
        __syncthreads();
    }
    float4 bv4 = *(const float4*)&bias[nn0];
#pragma unroll
    for (int i = 0; i < 8; i++) {
        int row = mt * 128 + m0 + i;
        float4 o;
        o.x = sum2(acc[i][0]) + bv4.x; o.y = sum2(acc[i][1]) + bv4.y;
        o.z = sum2(acc[i][2]) + bv4.z; o.w = sum2(acc[i][3]) + bv4.w;
        *(float4*)&d_tv2[row * 128 + nt * 64 + nn0] = o;
    }
}

// ---------------- K5b: GLU + residual + LayerNorm ----------------
__global__ void __launch_bounds__(256) k5b_ln(
    const float* __restrict__ gamma, const float* __restrict__ beta,
    float* __restrict__ out)
{
    __shared__ float ssum[8], ssum2[8];
    int tid = threadIdx.x;
    int grp = tid >> 6;
    int j = tid & 63;
    int row = blockIdx.x * 4 + grp;

    float a = d_tv2[row * 128 + j];
    float g = d_tv2[row * 128 + 64 + j];
    float y = d_seq[row * 64 + j] + a * sigf(g);

    float s = y, s2 = y * y;
#pragma unroll
    for (int off = 16; off; off >>= 1) {
        s += __shfl_xor_sync(0xFFFFFFFFu, s, off);
        s2 += __shfl_xor_sync(0xFFFFFFFFu, s2, off);
    }
    int w = tid >> 5;
    if ((tid & 31) == 0) { ssum[w] = s; ssum2[w] = s2; }
    __syncthreads();
    float tot = ssum[grp * 2] + ssum[grp * 2 + 1];
    float tot2 = ssum2[grp * 2] + ssum2[grp * 2 + 1];
    float mu = tot * (1.f / 64.f);
    float var = tot2 * (1.f / 64.f) - mu * mu;
    float inv = rsqrtf(var + 1e-5f);
    out[row * 64 + j] = (y - mu) * inv * gamma[j] + beta[j];
}

// ---------------- launch ----------------
extern "C" void kernel_launch(void* const* d_in, const int* in_sizes, int n_in,
                              void* d_out, int out_size)
{
    const float* hist = (const float*)d_in[0];
    const float* W1   = (const float*)d_in[2];
    const float* b1   = (const float*)d_in[3];
    const float* W_ih = (const float*)d_in[4];
    const float* W_hh = (const float*)d_in[5];
    const float* b_ih = (const float*)d_in[6];
    const float* b_hh = (const float*)d_in[7];
    const float* Wq   = (const float*)d_in[8];
    const float* bq   = (const float*)d_in[9];
    const float* Wk   = (const float*)d_in[10];
    const float* bk   = (const float*)d_in[11];
    const float* Wv   = (const float*)d_in[12];
    const float* bv   = (const float*)d_in[13];
    const float* Wa   = (const float*)d_in[14];
    const float* ba   = (const float*)d_in[15];
    const float* Wg   = (const float*)d_in[16];
    const float* bg   = (const float*)d_in[17];
    const float* gamma= (const float*)d_in[18];
    const float* beta = (const float*)d_in[19];
    float* out = (float*)d_out;

    k1_embed_gates<<<ROWS / 8, 256>>>(hist, W1, b1, W_ih, b_ih, b_hh);
    k2_lstm<<<BATCH, 256>>>(W_hh);
    k3_qkv<<<dim3(ROWS / 128, 9), 256>>>(Wq, bq, Wk, bk, Wv, bv);
    k4_attn<<<dim3(SEQ, NH), 160>>>();
    k5a_glu_gemm<<<dim3(ROWS / 128, 2), 256>>>(Wa, ba, Wg, bg);
    k5b_ln<<<ROWS / 4, 256>>>(gamma, beta, out);
}